// round 10
// baseline (speedup 1.0000x reference)
#include <cuda_runtime.h>

// MaxPool2d: kernel=2, stride=2, padding=0
// Input:  (32, 64, 224, 224) fp32  -> NC = 2048 planes of 224x224
// Output: (32, 64, 112, 112) fp32
//
// R9: identical memory pattern to R6/R8 (best: 75.2us), regrouped into
//     512-thread CTAs. Unit = (plane, output row, float4 chunk): thread
//     loads consecutive-16B float4 from rows 2oh and 2oh+1 (fully
//     coalesced LDG.128, 4 lines/instr), vertical+horizontal max ->
//     coalesced float2 store. 2 warp-strided units/thread (MLP=4).
//     12,845,056 units == 12544 blocks * 1024. No tail, no guard.
//     Occupancy unchanged (regs 32: 4 CTA/SM x 512 = 2048 thr resident).

#define IN_H    224
#define IN_W    224
#define OUT_H   112
#define OUT_W   112
#define NC      (32 * 64)

#define C4      (IN_W / 4)                  // 56 float4 chunks per input row
#define TOTAL   (NC * OUT_H * C4)           // 12,845,056 == 12544 * 1024

__device__ __forceinline__ void unit(unsigned g,
                                     const float* __restrict__ in,
                                     float* __restrict__ out)
{
    // 32-bit div/mod by constants -> magic-multiply IMADs
    const unsigned c4  = g % C4;
    const unsigned tmp = g / C4;
    const unsigned oh  = tmp % OUT_H;
    const unsigned nc  = tmp / OUT_H;

    const float* p = in + (size_t)nc * (IN_H * IN_W)
                        + (size_t)(2u * oh) * IN_W
                        + c4 * 4u;

    // Two fully-coalesced LDG.128 (lanes -> consecutive 16B)
    const float4 a = *reinterpret_cast<const float4*>(p);
    const float4 b = *reinterpret_cast<const float4*>(p + IN_W);

    // vertical max, then horizontal pair max -> 2 outputs
    float2 o;
    o.x = fmaxf(fmaxf(a.x, b.x), fmaxf(a.y, b.y));
    o.y = fmaxf(fmaxf(a.z, b.z), fmaxf(a.w, b.w));

    float* q = out + (size_t)nc * (OUT_H * OUT_W)
                   + (size_t)oh * OUT_W
                   + c4 * 2u;
    *reinterpret_cast<float2*>(q) = o;
}

__global__ __launch_bounds__(512)
void maxpool2d_k2s2_kernel(const float* __restrict__ in,
                           float* __restrict__ out)
{
    const unsigned base = blockIdx.x * 1024u + threadIdx.x;
    // two warp-strided units -> 4 front-batched loads (MLP=4)
    unit(base,        in, out);
    unit(base + 512u, in, out);
}

extern "C" void kernel_launch(void* const* d_in, const int* in_sizes, int n_in,
                              void* d_out, int out_size)
{
    const float* x = (const float*)d_in[0];
    float* y = (float*)d_out;

    maxpool2d_k2s2_kernel<<<TOTAL / 1024, 512>>>(x, y);   // 12544 blocks, exact
}